// round 3
// baseline (speedup 1.0000x reference)
#include <cuda_runtime.h>

// Problem constants (match reference)
#define B   16
#define LX  2048
#define LR  1024
#define D   768
#define T   (LX + LR + 3)   // 3075
#define D4  (D / 4)         // 192 float4 per row
#define RPB 4               // rows per CTA (B*T = 49200 divisible by 4)

// out[b,t,:] =
//   t == 0                          : CLS
//   1 <= t <= lx[b]                 : X[b, t-1]
//   t == lx[b]+1                    : RING
//   lx[b]+2 <= t < lx[b]+2+lr[b]    : Xr[b, t-lx[b]-2]
//   t == lx[b]+lr[b]+2              : END
//   else                            : 0
//
// Cache policy: output is written with default write-back stores so dirty
// lines can stay resident in L2 across graph replays (output ~151MB vs
// ~126MB L2 -> partial retention saves DRAM write traffic). X/Xr reads are
// single-use per replay -> streaming (__ldcs, evict-first) so they don't
// displace output lines.
__global__ __launch_bounds__(D4) void assemble_kernel(
    const float4* __restrict__ X,
    const float4* __restrict__ Xr,
    const float4* __restrict__ CLS,
    const float4* __restrict__ RING,
    const float4* __restrict__ END,
    const int*    __restrict__ lx,
    const int*    __restrict__ lr,
    float4*       __restrict__ out)
{
    const int c    = threadIdx.x;            // 0..191
    const int row0 = blockIdx.x * RPB;       // first of RPB consecutive rows

    float4 v[RPB];

    #pragma unroll
    for (int i = 0; i < RPB; i++) {
        const int row = row0 + i;
        const int b   = row / T;              // const-div -> mul/shift
        const int t   = row - b * T;

        const int lxb = __ldg(&lx[b]);
        const int lrb = __ldg(&lr[b]);

        if (t == 0) {
            v[i] = CLS[c];
        } else if (t <= lxb) {
            v[i] = __ldcs(&X[((long)b * LX + (t - 1)) * D4 + c]);
        } else if (t == lxb + 1) {
            v[i] = RING[c];
        } else if (t < lxb + 2 + lrb) {
            v[i] = __ldcs(&Xr[((long)b * LR + (t - lxb - 2)) * D4 + c]);
        } else if (t == lxb + lrb + 2) {
            v[i] = END[c];
        } else {
            v[i] = make_float4(0.f, 0.f, 0.f, 0.f);
        }
    }

    #pragma unroll
    for (int i = 0; i < RPB; i++) {
        out[(long)(row0 + i) * D4 + c] = v[i];   // default write-back (L2 resident)
    }
}

extern "C" void kernel_launch(void* const* d_in, const int* in_sizes, int n_in,
                              void* d_out, int out_size)
{
    const float4* X    = (const float4*)d_in[0];
    const float4* Xr   = (const float4*)d_in[1];
    const float4* CLS  = (const float4*)d_in[2];
    const float4* RING = (const float4*)d_in[3];
    const float4* END  = (const float4*)d_in[4];
    const int*    lx   = (const int*)d_in[5];
    const int*    lr   = (const int*)d_in[6];
    float4*       out  = (float4*)d_out;

    dim3 grid((B * T) / RPB);   // 12300 CTAs
    dim3 block(D4);             // 192 threads
    assemble_kernel<<<grid, block>>>(X, Xr, CLS, RING, END, lx, lr, out);
}

// round 5
// speedup vs baseline: 1.0086x; 1.0086x over previous
#include <cuda_runtime.h>

// Problem constants (match reference)
#define B   16
#define LX  2048
#define LR  1024
#define D   768
#define T   (LX + LR + 3)   // 3075
#define C8  (D / 8)         // 96 chunks of 8 floats (32B) per row
#define RPB 4               // rows per CTA (B*T = 49200 divisible by 4)

// Cache policy:
//  - X/Xr gather reads: touched working set (~75MB avg) fits in 126MB L2.
//    ld.global.nc.L2::evict_last (requires 256-bit form on sm_103) keeps
//    them resident across CUDA-graph replays -> L2 hits after 1st replay.
//  - Output stores (151MB, rewritten every replay, never read):
//    st.global.cs (evict_first) streams through without displacing reads.

__device__ __forceinline__ void ldg_keep32(const void* p, float4& a, float4& b) {
    unsigned long long r0, r1, r2, r3;
    asm volatile("ld.global.nc.L2::evict_last.v4.b64 {%0,%1,%2,%3}, [%4];"
                 : "=l"(r0), "=l"(r1), "=l"(r2), "=l"(r3)
                 : "l"(p));
    a.x = __uint_as_float((unsigned)(r0));       a.y = __uint_as_float((unsigned)(r0 >> 32));
    a.z = __uint_as_float((unsigned)(r1));       a.w = __uint_as_float((unsigned)(r1 >> 32));
    b.x = __uint_as_float((unsigned)(r2));       b.y = __uint_as_float((unsigned)(r2 >> 32));
    b.z = __uint_as_float((unsigned)(r3));       b.w = __uint_as_float((unsigned)(r3 >> 32));
}

__device__ __forceinline__ void stg_stream32(void* p, float4 a, float4 b) {
    unsigned long long r0 = (unsigned long long)__float_as_uint(a.x) |
                            ((unsigned long long)__float_as_uint(a.y) << 32);
    unsigned long long r1 = (unsigned long long)__float_as_uint(a.z) |
                            ((unsigned long long)__float_as_uint(a.w) << 32);
    unsigned long long r2 = (unsigned long long)__float_as_uint(b.x) |
                            ((unsigned long long)__float_as_uint(b.y) << 32);
    unsigned long long r3 = (unsigned long long)__float_as_uint(b.z) |
                            ((unsigned long long)__float_as_uint(b.w) << 32);
    asm volatile("st.global.cs.v4.b64 [%0], {%1,%2,%3,%4};"
                 :: "l"(p), "l"(r0), "l"(r1), "l"(r2), "l"(r3)
                 : "memory");
}

// out[b,t,:] =
//   t == 0                          : CLS
//   1 <= t <= lx[b]                 : X[b, t-1]
//   t == lx[b]+1                    : RING
//   lx[b]+2 <= t < lx[b]+2+lr[b]    : Xr[b, t-lx[b]-2]
//   t == lx[b]+lr[b]+2              : END
//   else                            : 0
__global__ __launch_bounds__(2 * C8) void assemble_kernel(
    const float*  __restrict__ X,
    const float*  __restrict__ Xr,
    const float4* __restrict__ CLS,
    const float4* __restrict__ RING,
    const float4* __restrict__ END,
    const int*    __restrict__ lx,
    const int*    __restrict__ lr,
    float*        __restrict__ out)
{
    // 192 threads = two 96-thread groups (3 warps each, no warp divergence).
    // Each group handles one row; each thread moves one 32B chunk.
    const int half = threadIdx.x / C8;        // 0 or 1
    const int c    = threadIdx.x - half * C8; // 0..95
    const int row0 = blockIdx.x * RPB;

    #pragma unroll
    for (int i = 0; i < RPB / 2; i++) {
        const int row = row0 + i * 2 + half;
        const int b   = row / T;               // const-div -> mul/shift
        const int t   = row - b * T;

        const int lxb = __ldg(&lx[b]);
        const int lrb = __ldg(&lr[b]);

        float4 va, vb;
        if (t == 0) {
            va = CLS[2 * c]; vb = CLS[2 * c + 1];
        } else if (t <= lxb) {
            ldg_keep32(X + ((long)b * LX + (t - 1)) * D + c * 8, va, vb);
        } else if (t == lxb + 1) {
            va = RING[2 * c]; vb = RING[2 * c + 1];
        } else if (t < lxb + 2 + lrb) {
            ldg_keep32(Xr + ((long)b * LR + (t - lxb - 2)) * D + c * 8, va, vb);
        } else if (t == lxb + lrb + 2) {
            va = END[2 * c]; vb = END[2 * c + 1];
        } else {
            va = make_float4(0.f, 0.f, 0.f, 0.f);
            vb = va;
        }

        stg_stream32(out + (long)row * D + c * 8, va, vb);
    }
}

extern "C" void kernel_launch(void* const* d_in, const int* in_sizes, int n_in,
                              void* d_out, int out_size)
{
    const float*  X    = (const float*)d_in[0];
    const float*  Xr   = (const float*)d_in[1];
    const float4* CLS  = (const float4*)d_in[2];
    const float4* RING = (const float4*)d_in[3];
    const float4* END  = (const float4*)d_in[4];
    const int*    lx   = (const int*)d_in[5];
    const int*    lr   = (const int*)d_in[6];
    float*        out  = (float*)d_out;

    dim3 grid((B * T) / RPB);   // 12300 CTAs
    dim3 block(2 * C8);         // 192 threads
    assemble_kernel<<<grid, block>>>(X, Xr, CLS, RING, END, lx, lr, out);
}

// round 6
// speedup vs baseline: 1.0133x; 1.0047x over previous
#include <cuda_runtime.h>

// Problem constants (match reference)
#define B   16
#define LX  2048
#define LR  1024
#define D   768
#define T   (LX + LR + 3)   // 3075
#define C8  (D / 8)         // 96 chunks of 8 floats (32B) per row
#define RPB 4               // rows per CTA (B*T = 49200 divisible by 4)

// Cache policy (steady-state across CUDA-graph replays):
// working set = 226MB > 126MB L2 -> nothing can be retained. Best policy is
// to keep L2 maximally out of the way: evict-first on BOTH the gather reads
// and the output stores (the R2 policy, which had the smallest steady-state
// overhead), expressed on 256-bit accesses (the R5 structure, which had the
// fastest cold-kernel time).

__device__ __forceinline__ void ldg_stream32(const void* p, float4& a, float4& b) {
    unsigned long long r0, r1, r2, r3;
    asm volatile("ld.global.nc.L2::evict_first.v4.b64 {%0,%1,%2,%3}, [%4];"
                 : "=l"(r0), "=l"(r1), "=l"(r2), "=l"(r3)
                 : "l"(p));
    a.x = __uint_as_float((unsigned)(r0));       a.y = __uint_as_float((unsigned)(r0 >> 32));
    a.z = __uint_as_float((unsigned)(r1));       a.w = __uint_as_float((unsigned)(r1 >> 32));
    b.x = __uint_as_float((unsigned)(r2));       b.y = __uint_as_float((unsigned)(r2 >> 32));
    b.z = __uint_as_float((unsigned)(r3));       b.w = __uint_as_float((unsigned)(r3 >> 32));
}

__device__ __forceinline__ void stg_stream32(void* p, float4 a, float4 b) {
    unsigned long long r0 = (unsigned long long)__float_as_uint(a.x) |
                            ((unsigned long long)__float_as_uint(a.y) << 32);
    unsigned long long r1 = (unsigned long long)__float_as_uint(a.z) |
                            ((unsigned long long)__float_as_uint(a.w) << 32);
    unsigned long long r2 = (unsigned long long)__float_as_uint(b.x) |
                            ((unsigned long long)__float_as_uint(b.y) << 32);
    unsigned long long r3 = (unsigned long long)__float_as_uint(b.z) |
                            ((unsigned long long)__float_as_uint(b.w) << 32);
    asm volatile("st.global.cs.v4.b64 [%0], {%1,%2,%3,%4};"
                 :: "l"(p), "l"(r0), "l"(r1), "l"(r2), "l"(r3)
                 : "memory");
}

// out[b,t,:] =
//   t == 0                          : CLS
//   1 <= t <= lx[b]                 : X[b, t-1]
//   t == lx[b]+1                    : RING
//   lx[b]+2 <= t < lx[b]+2+lr[b]    : Xr[b, t-lx[b]-2]
//   t == lx[b]+lr[b]+2              : END
//   else                            : 0
__global__ __launch_bounds__(2 * C8) void assemble_kernel(
    const float*  __restrict__ X,
    const float*  __restrict__ Xr,
    const float4* __restrict__ CLS,
    const float4* __restrict__ RING,
    const float4* __restrict__ END,
    const int*    __restrict__ lx,
    const int*    __restrict__ lr,
    float*        __restrict__ out)
{
    // 192 threads = two 96-thread groups (3 warps each, no warp divergence).
    // Each group handles one row; each thread moves one 32B chunk.
    const int half = threadIdx.x / C8;        // 0 or 1
    const int c    = threadIdx.x - half * C8; // 0..95
    const int row0 = blockIdx.x * RPB;

    #pragma unroll
    for (int i = 0; i < RPB / 2; i++) {
        const int row = row0 + i * 2 + half;
        const int b   = row / T;               // const-div -> mul/shift
        const int t   = row - b * T;

        const int lxb = __ldg(&lx[b]);
        const int lrb = __ldg(&lr[b]);

        float4 va, vb;
        if (t == 0) {
            va = CLS[2 * c]; vb = CLS[2 * c + 1];
        } else if (t <= lxb) {
            ldg_stream32(X + ((long)b * LX + (t - 1)) * D + c * 8, va, vb);
        } else if (t == lxb + 1) {
            va = RING[2 * c]; vb = RING[2 * c + 1];
        } else if (t < lxb + 2 + lrb) {
            ldg_stream32(Xr + ((long)b * LR + (t - lxb - 2)) * D + c * 8, va, vb);
        } else if (t == lxb + lrb + 2) {
            va = END[2 * c]; vb = END[2 * c + 1];
        } else {
            va = make_float4(0.f, 0.f, 0.f, 0.f);
            vb = va;
        }

        stg_stream32(out + (long)row * D + c * 8, va, vb);
    }
}

extern "C" void kernel_launch(void* const* d_in, const int* in_sizes, int n_in,
                              void* d_out, int out_size)
{
    const float*  X    = (const float*)d_in[0];
    const float*  Xr   = (const float*)d_in[1];
    const float4* CLS  = (const float4*)d_in[2];
    const float4* RING = (const float4*)d_in[3];
    const float4* END  = (const float4*)d_in[4];
    const int*    lx   = (const int*)d_in[5];
    const int*    lr   = (const int*)d_in[6];
    float*        out  = (float*)d_out;

    dim3 grid((B * T) / RPB);   // 12300 CTAs
    dim3 block(2 * C8);         // 192 threads
    assemble_kernel<<<grid, block>>>(X, Xr, CLS, RING, END, lx, lr, out);
}